// round 1
// baseline (speedup 1.0000x reference)
#include <cuda_runtime.h>
#include <cuda_bf16.h>
#include <math.h>

#define B_   16
#define N_   2048
#define F_   64
#define HD   256
#define GD   18
#define KD   128
#define FUSE 274
#define LN_EPS 1e-5f

// Scratch (device globals; no runtime allocation allowed)
__device__ float g_T[B_ * N_ * F_];     // A @ X            (8 MB)
__device__ float g_H1[B_ * N_ * HD];    // layer-1 output   (32 MB)
__device__ float g_S[B_ * N_ * HD];     // A @ H1           (32 MB)
__device__ float g_colsum[B_ * HD];     // readout partial sums

// ---------------------------------------------------------------------------
// Kernel 0: zero the readout accumulator (graph replays need a fresh state)
// ---------------------------------------------------------------------------
__global__ void k_zero_colsum() {
    g_colsum[blockIdx.x * 256 + threadIdx.x] = 0.f;
}

// ---------------------------------------------------------------------------
// Kernel 1: T[b] = A[b] (2048x2048) @ X[b] (2048x64)
// BM=128, BN=64(=F), BK=32, 256 threads, 8x4 register tile
// ---------------------------------------------------------------------------
__global__ __launch_bounds__(256)
void k_gemm_ax(const float* __restrict__ A, const float* __restrict__ X) {
    __shared__ float As[32][132];   // padded, stored transposed [k][m]
    __shared__ float Xs[32][64];

    const int b  = blockIdx.z;
    const int m0 = blockIdx.x * 128;
    const float* Ab = A + (size_t)b * N_ * N_;
    const float* Xb = X + (size_t)b * N_ * F_;

    const int tid = threadIdx.x;
    const int ty  = tid >> 4;   // 0..15 -> rows ty*8..+7
    const int tx  = tid & 15;   // 0..15 -> cols tx*4..+3

    float acc[8][4];
#pragma unroll
    for (int i = 0; i < 8; i++)
#pragma unroll
        for (int j = 0; j < 4; j++) acc[i][j] = 0.f;

    for (int k0 = 0; k0 < N_; k0 += 32) {
        // A tile: 128x32 = 1024 float4, 4 per thread (transposed store)
#pragma unroll
        for (int i = 0; i < 4; i++) {
            int f4  = tid + i * 256;
            int row = f4 >> 3;       // 8 float4 per row
            int c4  = f4 & 7;
            float4 v = *(const float4*)(Ab + (size_t)(m0 + row) * N_ + k0 + c4 * 4);
            As[c4 * 4 + 0][row] = v.x;
            As[c4 * 4 + 1][row] = v.y;
            As[c4 * 4 + 2][row] = v.z;
            As[c4 * 4 + 3][row] = v.w;
        }
        // X tile: 32x64 = 512 float4, 2 per thread
#pragma unroll
        for (int i = 0; i < 2; i++) {
            int f4  = tid + i * 256;
            int row = f4 >> 4;       // 16 float4 per row
            int c4  = f4 & 15;
            *(float4*)&Xs[row][c4 * 4] =
                *(const float4*)(Xb + (size_t)(k0 + row) * F_ + c4 * 4);
        }
        __syncthreads();

#pragma unroll
        for (int k = 0; k < 32; k++) {
            float4 a0 = *(const float4*)&As[k][ty * 8];
            float4 a1 = *(const float4*)&As[k][ty * 8 + 4];
            float4 xv = *(const float4*)&Xs[k][tx * 4];
            float a[8] = {a0.x, a0.y, a0.z, a0.w, a1.x, a1.y, a1.z, a1.w};
            float x[4] = {xv.x, xv.y, xv.z, xv.w};
#pragma unroll
            for (int i = 0; i < 8; i++)
#pragma unroll
                for (int j = 0; j < 4; j++) acc[i][j] += a[i] * x[j];
        }
        __syncthreads();
    }

    float* Tb = g_T + (size_t)b * N_ * F_;
#pragma unroll
    for (int i = 0; i < 8; i++) {
        float4 v = {acc[i][0], acc[i][1], acc[i][2], acc[i][3]};
        *(float4*)&Tb[(size_t)(m0 + ty * 8 + i) * F_ + tx * 4] = v;
    }
}

// ---------------------------------------------------------------------------
// Kernel 3: S[b] = A[b] (2048x2048) @ H1[b] (2048x256)
// BM=128, BN=128, BK=16, 256 threads, 8x8 register tile
// ---------------------------------------------------------------------------
__global__ __launch_bounds__(256)
void k_gemm_ah(const float* __restrict__ A) {
    __shared__ float As[16][132];
    __shared__ float Bs[16][128];

    const int b  = blockIdx.z;
    const int m0 = blockIdx.x * 128;
    const int n0 = blockIdx.y * 128;
    const float* Ab = A + (size_t)b * N_ * N_;
    const float* Hb = g_H1 + (size_t)b * N_ * HD;

    const int tid = threadIdx.x;
    const int ty  = tid >> 4;
    const int tx  = tid & 15;

    float acc[8][8];
#pragma unroll
    for (int i = 0; i < 8; i++)
#pragma unroll
        for (int j = 0; j < 8; j++) acc[i][j] = 0.f;

    for (int k0 = 0; k0 < N_; k0 += 16) {
        // A tile: 128x16 = 512 float4, 2 per thread (transposed store)
#pragma unroll
        for (int i = 0; i < 2; i++) {
            int f4  = tid + i * 256;
            int row = f4 >> 2;       // 4 float4 per row
            int c4  = f4 & 3;
            float4 v = *(const float4*)(Ab + (size_t)(m0 + row) * N_ + k0 + c4 * 4);
            As[c4 * 4 + 0][row] = v.x;
            As[c4 * 4 + 1][row] = v.y;
            As[c4 * 4 + 2][row] = v.z;
            As[c4 * 4 + 3][row] = v.w;
        }
        // H tile: 16x128 = 512 float4, 2 per thread
#pragma unroll
        for (int i = 0; i < 2; i++) {
            int f4  = tid + i * 256;
            int row = f4 >> 5;       // 32 float4 per row
            int c4  = f4 & 31;
            *(float4*)&Bs[row][c4 * 4] =
                *(const float4*)(Hb + (size_t)(k0 + row) * HD + n0 + c4 * 4);
        }
        __syncthreads();

#pragma unroll
        for (int k = 0; k < 16; k++) {
            float4 a0 = *(const float4*)&As[k][ty * 8];
            float4 a1 = *(const float4*)&As[k][ty * 8 + 4];
            float4 b0 = *(const float4*)&Bs[k][tx * 8];
            float4 b1 = *(const float4*)&Bs[k][tx * 8 + 4];
            float a[8] = {a0.x, a0.y, a0.z, a0.w, a1.x, a1.y, a1.z, a1.w};
            float h[8] = {b0.x, b0.y, b0.z, b0.w, b1.x, b1.y, b1.z, b1.w};
#pragma unroll
            for (int i = 0; i < 8; i++)
#pragma unroll
                for (int j = 0; j < 8; j++) acc[i][j] += a[i] * h[j];
        }
        __syncthreads();
    }

    float* Sb = g_S + (size_t)b * N_ * HD;
#pragma unroll
    for (int i = 0; i < 8; i++) {
        float4 v0 = {acc[i][0], acc[i][1], acc[i][2], acc[i][3]};
        float4 v1 = {acc[i][4], acc[i][5], acc[i][6], acc[i][7]};
        float* row = &Sb[(size_t)(m0 + ty * 8 + i) * HD + n0 + tx * 8];
        *(float4*)row       = v0;
        *(float4*)(row + 4) = v1;
    }
}

// ---------------------------------------------------------------------------
// Kernels 2/4: per-row  relu(LN(In @ W + bias))
//   LAYER==1: In = g_T  (KDIM=64),  write g_H1
//   LAYER==2: In = g_S  (KDIM=256), accumulate column mean into g_colsum
// 256 threads = 1 thread per output channel; W tiled through smem in KC=32 chunks
// ---------------------------------------------------------------------------
template <int LAYER>
__global__ __launch_bounds__(256)
void k_linear_ln_relu(const float* __restrict__ W, const float* __restrict__ bias,
                      const float* __restrict__ gamma, const float* __restrict__ beta) {
    constexpr int KDIM = (LAYER == 1) ? F_ : HD;
    constexpr int RPB  = (LAYER == 1) ? 32 : 16;
    constexpr int KC   = 32;

    __shared__ float w_s[KC * HD];       // 32 KB
    __shared__ float t_s[RPB][KC];
    __shared__ float red[2][8];

    const float* In = (LAYER == 1) ? g_T : g_S;
    const int c  = threadIdx.x;          // output channel 0..255
    const int r0 = blockIdx.x * RPB;     // flat row (b*N + n); RPB divides N_

    float acc[RPB];
#pragma unroll
    for (int r = 0; r < RPB; r++) acc[r] = 0.f;

    for (int k0 = 0; k0 < KDIM; k0 += KC) {
        __syncthreads();
        // W chunk: KC x 256 floats = KC*64 float4
#pragma unroll
        for (int i = 0; i < KC / 4; i++) {
            int f4 = c + i * 256;
            int kk = f4 >> 6;
            int c4 = f4 & 63;
            *(float4*)&w_s[kk * HD + c4 * 4] =
                *(const float4*)(W + (size_t)(k0 + kk) * HD + c4 * 4);
        }
        // Input rows chunk: RPB x KC floats
        for (int idx = c; idx < RPB * (KC / 4); idx += 256) {
            int r  = idx / (KC / 4);
            int c4 = idx % (KC / 4);
            *(float4*)&t_s[r][c4 * 4] =
                *(const float4*)(In + (size_t)(r0 + r) * KDIM + k0 + c4 * 4);
        }
        __syncthreads();

#pragma unroll
        for (int kk = 0; kk < KC; kk++) {
            float wv = w_s[kk * HD + c];
#pragma unroll
            for (int r = 0; r < RPB; r++) acc[r] += t_s[r][kk] * wv;
        }
    }

    const float bv  = bias[c];
    const float gv  = gamma[c];
    const float btv = beta[c];
    const int lane = c & 31;
    const int wid  = c >> 5;
    float rowsum = 0.f;

#pragma unroll 1
    for (int r = 0; r < RPB; r++) {
        float v = acc[r] + bv;
        float s = v, sq = v * v;
#pragma unroll
        for (int o = 16; o > 0; o >>= 1) {
            s  += __shfl_xor_sync(0xffffffff, s,  o);
            sq += __shfl_xor_sync(0xffffffff, sq, o);
        }
        if (lane == 0) { red[0][wid] = s; red[1][wid] = sq; }
        __syncthreads();
        if (wid == 0) {
            float s2  = (lane < 8) ? red[0][lane] : 0.f;
            float sq2 = (lane < 8) ? red[1][lane] : 0.f;
#pragma unroll
            for (int o = 4; o > 0; o >>= 1) {
                s2  += __shfl_xor_sync(0xffffffff, s2,  o);
                sq2 += __shfl_xor_sync(0xffffffff, sq2, o);
            }
            if (lane == 0) { red[0][0] = s2; red[1][0] = sq2; }
        }
        __syncthreads();
        float mu  = red[0][0] * (1.f / HD);
        float var = red[1][0] * (1.f / HD) - mu * mu;
        float y = (v - mu) * rsqrtf(var + LN_EPS) * gv + btv;
        y = fmaxf(y, 0.f);
        if (LAYER == 1) g_H1[(size_t)(r0 + r) * HD + c] = y;
        else            rowsum += y;
        __syncthreads();   // protect red[] before next row
    }

    if (LAYER == 2) {
        int b = r0 / N_;   // RPB divides N_, block never straddles batches
        atomicAdd(&g_colsum[b * HD + c], rowsum);
    }
}

// ---------------------------------------------------------------------------
// Kernel 5: readout + heads. One block per batch.
// out[0..15] = pred_y ; out[16 .. 16+B*K) = pred_arr row-major
// ---------------------------------------------------------------------------
__global__ __launch_bounds__(288)
void k_finalize(const float* __restrict__ gvec,
                const float* __restrict__ Ws, const float* __restrict__ bs,
                const float* __restrict__ Wa, const float* __restrict__ ba,
                float* __restrict__ out) {
    __shared__ float fused[FUSE];
    const int b = blockIdx.x;
    const int t = threadIdx.x;

    if (t < HD)            fused[t] = g_colsum[b * HD + t] * (1.f / N_);
    else if (t < FUSE)     fused[t] = gvec[b * GD + (t - HD)];
    __syncthreads();

    if (t < KD) {
        float a = ba[t];
#pragma unroll 2
        for (int i = 0; i < FUSE; i++) a += fused[i] * Wa[i * KD + t];
        out[B_ + b * KD + t] = a;
    } else if (t == KD) {
        float a = bs[0];
        for (int i = 0; i < FUSE; i++) a += fused[i] * Ws[i];
        out[b] = a;
    }
}

// ---------------------------------------------------------------------------
extern "C" void kernel_launch(void* const* d_in, const int* in_sizes, int n_in,
                              void* d_out, int out_size) {
    const float* A    = (const float*)d_in[0];
    const float* X    = (const float*)d_in[1];
    const float* gvec = (const float*)d_in[2];
    const float* W1   = (const float*)d_in[3];
    const float* b1   = (const float*)d_in[4];
    const float* g1   = (const float*)d_in[5];
    const float* be1  = (const float*)d_in[6];
    const float* W2   = (const float*)d_in[7];
    const float* b2   = (const float*)d_in[8];
    const float* g2   = (const float*)d_in[9];
    const float* be2  = (const float*)d_in[10];
    const float* Ws   = (const float*)d_in[11];
    const float* bs   = (const float*)d_in[12];
    const float* Wa   = (const float*)d_in[13];
    const float* ba   = (const float*)d_in[14];
    float* out = (float*)d_out;

    k_zero_colsum<<<B_, 256>>>();

    // Layer 1
    k_gemm_ax<<<dim3(N_ / 128, 1, B_), 256>>>(A, X);
    k_linear_ln_relu<1><<<(B_ * N_) / 32, 256>>>(W1, b1, g1, be1);

    // Layer 2
    k_gemm_ah<<<dim3(N_ / 128, HD / 128, B_), 256>>>(A);
    k_linear_ln_relu<2><<<(B_ * N_) / 16, 256>>>(W2, b2, g2, be2);

    // Readout + heads
    k_finalize<<<B_, 288>>>(gvec, Ws, bs, Wa, ba, out);
}

// round 3
// speedup vs baseline: 5.1039x; 5.1039x over previous
#include <cuda_runtime.h>
#include <cstdint>
#include <math.h>

#define B_   16
#define N_   2048
#define F_   64
#define HD   256
#define GD   18
#define KD   128
#define FUSE 274
#define LN_EPS 1e-5f

// tcgen05 is arch-accelerated: only available when compiling for sm_100a/sm_103a
// (or family-specific) targets. The harness also runs a plain compute_103 pass,
// which must compile — those passes get a SIMT fallback body instead.
#if defined(__CUDA_ARCH_FEAT_SM103_ALL) || defined(__CUDA_ARCH_FEAT_SM100_ALL) || \
    defined(__CUDA_ARCH_FEAT_SM101_ALL) || \
    (defined(__CUDA_ARCH_SPECIFIC__) && (__CUDA_ARCH_SPECIFIC__ >= 1000)) || \
    (defined(__CUDA_ARCH_FAMILY_SPECIFIC__) && (__CUDA_ARCH_FAMILY_SPECIFIC__ >= 1000))
#define TC_OK 1
#else
#define TC_OK 0
#endif

// ---------------------------------------------------------------------------
// Scratch (device globals; no runtime allocation allowed)
// ---------------------------------------------------------------------------
__device__ __align__(1024) float g_P[B_ * HD * N_];    // P^T  [b][c][n]  (B-operand layout)
__device__ __align__(1024) float g_H1[B_ * N_ * HD];   // layer-1 output, row-major [b][n][c]
__device__ __align__(1024) float g_WT1[HD * F_];       // W1^T [c][k]
__device__ __align__(1024) float g_WT2[HD * HD];       // W2^T [c][k]
__device__ float g_colsum[B_ * HD];

// ---------------------------------------------------------------------------
// Helpers
// ---------------------------------------------------------------------------
__device__ __forceinline__ uint32_t smem_u32(const void* p) {
    uint32_t a;
    asm("{ .reg .u64 t; cvta.to.shared.u64 t, %1; cvt.u32.u64 %0, t; }" : "=r"(a) : "l"(p));
    return a;
}
#define SWZ(x) ((x) ^ (((x) >> 3) & 0x70))

__device__ __forceinline__ void cpa16(uint32_t dst, const void* src) {
    asm volatile("cp.async.cg.shared.global [%0], [%1], 16;\n" :: "r"(dst), "l"(src));
}
#define CP_COMMIT()  asm volatile("cp.async.commit_group;" ::: "memory")
#define CP_WAIT(n)   asm volatile("cp.async.wait_group %0;" :: "n"(n) : "memory")
#define FENCE_ASYNC() asm volatile("fence.proxy.async.shared::cta;" ::: "memory")
#define MBAR_INIT(a, c) \
    asm volatile("mbarrier.init.shared.b64 [%0], %1;" :: "r"(a), "r"(c) : "memory")

__device__ __forceinline__ void mbar_wait(uint32_t mbar, uint32_t parity) {
    asm volatile(
        "{\n\t.reg .pred P1;\n\t"
        "WL_%=:\n\t"
        "mbarrier.try_wait.parity.acquire.cta.shared::cta.b64 P1, [%0], %1, 0x989680;\n\t"
        "@P1 bra.uni WD_%=;\n\t"
        "bra.uni WL_%=;\n\t"
        "WD_%=:\n\t}"
        :: "r"(mbar), "r"(parity) : "memory");
}

#if TC_OK
__device__ __forceinline__ uint64_t sdesc(uint32_t addr) {
    // SW128, Blackwell version=1, SBO=64 (1024B = 8 rows x 128B), LBO=1
    return ((2ull << 61) | (1ull << 46) | (64ull << 32) | (1ull << 16))
         | ((uint64_t)(addr >> 4) & 0x3FFF);
}
#define TC_COMMIT(a) \
    asm volatile("tcgen05.commit.cta_group::1.mbarrier::arrive::one.shared::cluster.b64 [%0];" \
                 :: "r"(a) : "memory")
#define TC_ALLOC(a, n) \
    asm volatile("tcgen05.alloc.cta_group::1.sync.aligned.shared::cta.b32 [%0], %1;" \
                 :: "r"(a), "r"(n) : "memory")
#define TC_RELINQ() \
    asm volatile("tcgen05.relinquish_alloc_permit.cta_group::1.sync.aligned;")
#define TC_DEALLOC(t, n) \
    asm volatile("tcgen05.dealloc.cta_group::1.sync.aligned.b32 %0, %1;" :: "r"(t), "r"(n))
#define TC_FENCE_AFTER()  asm volatile("tcgen05.fence::after_thread_sync;" ::: "memory")
#define TC_WAIT_LD() asm volatile("tcgen05.wait::ld.sync.aligned;" ::: "memory")

// D = A @ B^T : fp32 accum, TF32 inputs (fmt=2), M=128, N=256
#define IDESC_TF32 ((1u << 4) | (2u << 7) | (2u << 10) | ((256u / 8) << 17) | ((128u / 16) << 24))

__device__ __forceinline__ void mma_tf32(uint32_t d, uint64_t ad, uint64_t bd, uint32_t acc) {
    asm volatile(
        "{\n\t.reg .pred p;\n\t"
        "setp.ne.u32 p, %4, 0;\n\t"
        "tcgen05.mma.cta_group::1.kind::tf32 [%0], %1, %2, %3, p;\n\t}"
        :: "r"(d), "l"(ad), "l"(bd), "r"(IDESC_TF32), "r"(acc) : "memory");
}

#define LDX32(r, a) \
    asm volatile( \
        "tcgen05.ld.sync.aligned.32x32b.x32.b32 " \
        "{%0, %1, %2, %3, %4, %5, %6, %7, %8, %9, %10, %11, %12, %13, %14, %15, " \
        " %16, %17, %18, %19, %20, %21, %22, %23, %24, %25, %26, %27, %28, %29, %30, %31}, [%32];" \
        : "=r"((r)[0]),  "=r"((r)[1]),  "=r"((r)[2]),  "=r"((r)[3]), \
          "=r"((r)[4]),  "=r"((r)[5]),  "=r"((r)[6]),  "=r"((r)[7]), \
          "=r"((r)[8]),  "=r"((r)[9]),  "=r"((r)[10]), "=r"((r)[11]), \
          "=r"((r)[12]), "=r"((r)[13]), "=r"((r)[14]), "=r"((r)[15]), \
          "=r"((r)[16]), "=r"((r)[17]), "=r"((r)[18]), "=r"((r)[19]), \
          "=r"((r)[20]), "=r"((r)[21]), "=r"((r)[22]), "=r"((r)[23]), \
          "=r"((r)[24]), "=r"((r)[25]), "=r"((r)[26]), "=r"((r)[27]), \
          "=r"((r)[28]), "=r"((r)[29]), "=r"((r)[30]), "=r"((r)[31]) \
        : "r"(a))
#endif // TC_OK

// ---------------------------------------------------------------------------
// misc small kernels (arch-neutral)
// ---------------------------------------------------------------------------
__global__ void k_zero_colsum() { g_colsum[blockIdx.x * 256 + threadIdx.x] = 0.f; }

__global__ void k_transpose(const float* __restrict__ W, float* __restrict__ WT, int K) {
    int c = threadIdx.x;
    for (int k = blockIdx.x; k < K; k += gridDim.x)
        WT[c * K + k] = W[k * 256 + c];
}

// ---------------------------------------------------------------------------
// Small GEMM: D[128 nodes, 256 c] = In[node, KDIM] @ WT[c, KDIM]^T ; write P^T
// ---------------------------------------------------------------------------
template <int KDIM>
__global__ __launch_bounds__(128, 1)
void k_small_gemm(const float* __restrict__ In, const float* __restrict__ WT) {
    const int tid = threadIdx.x;
    const int b   = blockIdx.y;
    const int m0  = blockIdx.x * 128;
    const float* Inb = In + (size_t)b * N_ * KDIM + (size_t)m0 * KDIM;
    float* PTb = g_P + (size_t)b * HD * N_;

#if TC_OK
    constexpr int NK = KDIM / 32;
    constexpr int STG = 48 * 1024;          // A 16KB + B 32KB per stage
    extern __shared__ char dyn[];
    uint32_t sbase = (smem_u32(dyn) + 1023) & ~1023u;

    __shared__ __align__(8) uint64_t s_bar[3];
    __shared__ uint32_t s_tmem[1];

    const int wid  = tid >> 5;
    const int lane = tid & 31;

    if (tid == 0) {
        uint32_t ba = smem_u32(s_bar);
        MBAR_INIT(ba, 1); MBAR_INIT(ba + 8, 1); MBAR_INIT(ba + 16, 1);
    }
    if (wid == 0) { TC_ALLOC(smem_u32(s_tmem), 256); TC_RELINQ(); }
    __syncthreads();
    uint32_t tmem;
    asm volatile("ld.shared.b32 %0, [%1];" : "=r"(tmem) : "r"(smem_u32(s_tmem)));
    const uint32_t bar0 = smem_u32(s_bar);

    const int rr = tid >> 3, cc = (tid & 7) * 16;

    auto load_tile = [&](int t) {
        uint32_t sa = sbase + (t & 1) * STG;
        uint32_t sb = sa + 16 * 1024;
        int k0 = t * 32;
#pragma unroll
        for (int i = 0; i < 8; i++) {
            int r = rr + i * 16;
            cpa16(sa + SWZ(r * 128 + cc), Inb + (size_t)r * KDIM + k0 + (cc >> 2));
        }
#pragma unroll
        for (int i = 0; i < 16; i++) {
            int r = rr + i * 16;
            cpa16(sb + SWZ(r * 128 + cc), WT + (size_t)r * KDIM + k0 + (cc >> 2));
        }
    };

    load_tile(0);
    CP_COMMIT();

#pragma unroll 1
    for (int t = 0; t < NK; t++) {
        int s = t & 1;
        CP_WAIT(0);
        FENCE_ASYNC();
        __syncthreads();
        if (tid == 0) {
            uint32_t sa = sbase + s * STG;
            uint64_t a0 = sdesc(sa), b0 = sdesc(sa + 16 * 1024);
#pragma unroll
            for (int ks = 0; ks < 4; ks++)
                mma_tf32(tmem, a0 + ks * 2, b0 + ks * 2, (t > 0 || ks > 0) ? 1u : 0u);
            TC_COMMIT(bar0 + s * 8);
        }
        int tn = t + 1;
        if (tn < NK) {
            if (t >= 1) mbar_wait(bar0 + (tn & 1) * 8, ((t - 1) / 2) & 1);
            load_tile(tn);
        }
        CP_COMMIT();
    }
    if (tid == 0) TC_COMMIT(bar0 + 16);
    mbar_wait(bar0 + 16, 0);
    TC_FENCE_AFTER();

    // epilogue: lane = node row; reg j = channel. Per-reg stores coalesced.
    const int row = m0 + wid * 32 + lane;
#pragma unroll
    for (int c8 = 0; c8 < 8; c8++) {
        uint32_t r[32];
        LDX32(r, tmem + c8 * 32);
        TC_WAIT_LD();
#pragma unroll
        for (int j = 0; j < 32; j++)
            PTb[(size_t)(c8 * 32 + j) * N_ + row] = __uint_as_float(r[j]);
    }
    __syncthreads();
    if (wid == 0) TC_DEALLOC(tmem, 256);
#else
    // ---- SIMT fallback (correctness insurance for non-'a' targets) ----
    for (int idx = tid; idx < 128 * 256; idx += 128) {
        int m = idx >> 8, c = idx & 255;
        float acc = 0.f;
        for (int k = 0; k < KDIM; k++)
            acc += Inb[(size_t)m * KDIM + k] * WT[(size_t)c * KDIM + k];
        PTb[(size_t)c * N_ + m0 + m] = acc;
    }
#endif
}

// ---------------------------------------------------------------------------
// Big GEMM + fused epilogue: D[256, 256] = A[b] @ P^T[b]^T ; y = relu(LN(D+b))
//   LAYER 1: y -> g_H1 ; LAYER 2: column-sum(y) -> g_colsum
// ---------------------------------------------------------------------------
template <int LAYER>
__global__ __launch_bounds__(128, 1)
void k_big_gemm(const float* __restrict__ A,
                const float* __restrict__ bias, const float* __restrict__ gamma,
                const float* __restrict__ beta) {
    extern __shared__ char dyn[];
    const int tid = threadIdx.x;
    const int b   = blockIdx.y;
    const int m0  = blockIdx.x * 256;
    const float* Ab = A + (size_t)b * N_ * N_ + (size_t)m0 * N_;
    const float* Bb = g_P + (size_t)b * HD * N_;

#if TC_OK
    constexpr int NK  = N_ / 32;            // 64
    constexpr int STG = 64 * 1024;          // A 32KB + B 32KB per stage
    uint32_t sbase = (smem_u32(dyn) + 1023) & ~1023u;

    __shared__ __align__(8) uint64_t s_bar[4];
    __shared__ uint32_t s_tmem[1];

    const int wid  = tid >> 5;
    const int lane = tid & 31;

    if (tid == 0) {
        uint32_t ba = smem_u32(s_bar);
        MBAR_INIT(ba, 1); MBAR_INIT(ba + 8, 1); MBAR_INIT(ba + 16, 1); MBAR_INIT(ba + 24, 1);
    }
    if (wid == 0) { TC_ALLOC(smem_u32(s_tmem), 512); TC_RELINQ(); }
    __syncthreads();
    uint32_t tmem;
    asm volatile("ld.shared.b32 %0, [%1];" : "=r"(tmem) : "r"(smem_u32(s_tmem)));
    const uint32_t bar0 = smem_u32(s_bar);

    const int rr = tid >> 3, cc = (tid & 7) * 16;

    auto load_tile = [&](int t) {
        int s = t % 3;
        uint32_t sa = sbase + s * STG;
        uint32_t sb = sa + 32 * 1024;
        int k0 = t * 32;
#pragma unroll
        for (int i = 0; i < 16; i++) {
            int r = rr + i * 16;
            cpa16(sa + SWZ(r * 128 + cc), Ab + (size_t)r * N_ + k0 + (cc >> 2));
        }
#pragma unroll
        for (int i = 0; i < 16; i++) {
            int r = rr + i * 16;
            cpa16(sb + SWZ(r * 128 + cc), Bb + (size_t)r * N_ + k0 + (cc >> 2));
        }
    };

    load_tile(0); CP_COMMIT();
    load_tile(1); CP_COMMIT();

#pragma unroll 1
    for (int t = 0; t < NK; t++) {
        int s = t % 3;
        CP_WAIT(1);
        FENCE_ASYNC();
        __syncthreads();
        if (tid == 0) {
            uint32_t sa = sbase + s * STG;
            uint64_t a0 = sdesc(sa), a1 = sdesc(sa + 16 * 1024), b0 = sdesc(sa + 32 * 1024);
#pragma unroll
            for (int ks = 0; ks < 4; ks++) {
                uint32_t acc = (t > 0 || ks > 0) ? 1u : 0u;
                mma_tf32(tmem,       a0 + ks * 2, b0 + ks * 2, acc);
                mma_tf32(tmem + 256, a1 + ks * 2, b0 + ks * 2, acc);
            }
            TC_COMMIT(bar0 + s * 8);
        }
        int tn = t + 2;
        if (tn < NK) {
            if (t >= 1) mbar_wait(bar0 + (tn % 3) * 8, ((t - 1) / 3) & 1);
            load_tile(tn);
        }
        CP_COMMIT();
    }
    if (tid == 0) TC_COMMIT(bar0 + 24);
    mbar_wait(bar0 + 24, 0);
    TC_FENCE_AFTER();

    // ---- epilogue (pipeline smem is free now) ----
    float* p_bias = (float*)(dyn);
    float* p_g    = p_bias + 256;
    float* p_bt   = p_g + 256;
    float* wsc    = p_bt + 256 + (wid * 33 * 32);
    for (int i = tid; i < 256; i += 128) {
        p_bias[i] = bias[i]; p_g[i] = gamma[i]; p_bt[i] = beta[i];
    }
    __syncthreads();

#pragma unroll 1
    for (int half = 0; half < 2; half++) {
        const int row = half * 128 + wid * 32 + lane;
        const uint32_t dbase = tmem + half * 256;
        float sum = 0.f, sq = 0.f;
#pragma unroll 1
        for (int c8 = 0; c8 < 8; c8++) {
            uint32_t r[32];
            LDX32(r, dbase + c8 * 32);
            TC_WAIT_LD();
#pragma unroll
            for (int j = 0; j < 32; j++) {
                float v = __uint_as_float(r[j]) + p_bias[c8 * 32 + j];
                sum += v; sq += v * v;
            }
        }
        const float mu  = sum * (1.f / HD);
        const float var = sq * (1.f / HD) - mu * mu;
        const float rs  = rsqrtf(var + LN_EPS);

#pragma unroll 1
        for (int c8 = 0; c8 < 8; c8++) {
            uint32_t r[32];
            LDX32(r, dbase + c8 * 32);
            TC_WAIT_LD();
            float y[32];
#pragma unroll
            for (int j = 0; j < 32; j++) {
                float v = __uint_as_float(r[j]) + p_bias[c8 * 32 + j];
                y[j] = fmaxf((v - mu) * rs * p_g[c8 * 32 + j] + p_bt[c8 * 32 + j], 0.f);
            }
            if (LAYER == 1) {
                float* dst = g_H1 + ((size_t)b * N_ + m0 + row) * HD + c8 * 32;
#pragma unroll
                for (int q = 0; q < 8; q++) {
                    float4 v4 = {y[q * 4], y[q * 4 + 1], y[q * 4 + 2], y[q * 4 + 3]};
                    *(float4*)(dst + q * 4) = v4;
                }
            } else {
#pragma unroll
                for (int j = 0; j < 32; j++) wsc[lane * 33 + j] = y[j];
                __syncwarp();
                float s2 = 0.f;
#pragma unroll
                for (int r2 = 0; r2 < 32; r2++) s2 += wsc[r2 * 33 + lane];
                atomicAdd(&g_colsum[b * HD + c8 * 32 + lane], s2);
                __syncwarp();
            }
        }
    }
    __syncthreads();
    if (wid == 0) TC_DEALLOC(tmem, 512);
#else
    // ---- SIMT fallback (correctness insurance for non-'a' targets) ----
    __shared__ float arow[N_];
    __shared__ float drow[256];
    __shared__ float red[2][4];
    const int lane = tid & 31, wid = tid >> 5;
    float csum0 = 0.f, csum1 = 0.f;

    for (int m = 0; m < 256; m++) {
        const int row = m0 + m;
        for (int i = tid; i < N_ / 4; i += 128)
            ((float4*)arow)[i] = ((const float4*)(Ab + (size_t)m * N_))[i];
        __syncthreads();
#pragma unroll
        for (int cp = 0; cp < 2; cp++) {
            int c = tid + cp * 128;
            float acc = 0.f;
            const float* Brow = Bb + (size_t)c * N_;
            for (int k = 0; k < N_; k++) acc += arow[k] * Brow[k];
            drow[c] = acc + bias[c];
        }
        __syncthreads();
        float v0 = drow[tid], v1 = drow[tid + 128];
        float s = v0 + v1, q = v0 * v0 + v1 * v1;
#pragma unroll
        for (int o = 16; o > 0; o >>= 1) {
            s += __shfl_xor_sync(0xffffffff, s, o);
            q += __shfl_xor_sync(0xffffffff, q, o);
        }
        if (lane == 0) { red[0][wid] = s; red[1][wid] = q; }
        __syncthreads();
        float ts = red[0][0] + red[0][1] + red[0][2] + red[0][3];
        float tq = red[1][0] + red[1][1] + red[1][2] + red[1][3];
        float mu = ts * (1.f / HD);
        float var = tq * (1.f / HD) - mu * mu;
        float rs = rsqrtf(var + LN_EPS);
        float y0 = fmaxf((v0 - mu) * rs * gamma[tid] + beta[tid], 0.f);
        float y1 = fmaxf((v1 - mu) * rs * gamma[tid + 128] + beta[tid + 128], 0.f);
        if (LAYER == 1) {
            g_H1[((size_t)b * N_ + row) * HD + tid]       = y0;
            g_H1[((size_t)b * N_ + row) * HD + tid + 128] = y1;
        } else {
            csum0 += y0; csum1 += y1;
        }
        __syncthreads();
    }
    if (LAYER == 2) {
        atomicAdd(&g_colsum[b * HD + tid], csum0);
        atomicAdd(&g_colsum[b * HD + tid + 128], csum1);
    }
#endif
}

// ---------------------------------------------------------------------------
// Readout + heads
// ---------------------------------------------------------------------------
__global__ __launch_bounds__(288)
void k_finalize(const float* __restrict__ gvec,
                const float* __restrict__ Ws, const float* __restrict__ bs,
                const float* __restrict__ Wa, const float* __restrict__ ba,
                float* __restrict__ out) {
    __shared__ float fused[FUSE];
    const int b = blockIdx.x;
    const int t = threadIdx.x;

    if (t < HD)        fused[t] = g_colsum[b * HD + t] * (1.f / N_);
    else if (t < FUSE) fused[t] = gvec[b * GD + (t - HD)];
    __syncthreads();

    if (t < KD) {
        float a = ba[t];
#pragma unroll 2
        for (int i = 0; i < FUSE; i++) a += fused[i] * Wa[i * KD + t];
        out[B_ + b * KD + t] = a;
    } else if (t == KD) {
        float a = bs[0];
        for (int i = 0; i < FUSE; i++) a += fused[i] * Ws[i];
        out[b] = a;
    }
}

// ---------------------------------------------------------------------------
extern "C" void kernel_launch(void* const* d_in, const int* in_sizes, int n_in,
                              void* d_out, int out_size) {
    const float* A    = (const float*)d_in[0];
    const float* X    = (const float*)d_in[1];
    const float* gvec = (const float*)d_in[2];
    const float* W1   = (const float*)d_in[3];
    const float* b1   = (const float*)d_in[4];
    const float* g1   = (const float*)d_in[5];
    const float* be1  = (const float*)d_in[6];
    const float* W2   = (const float*)d_in[7];
    const float* b2   = (const float*)d_in[8];
    const float* g2   = (const float*)d_in[9];
    const float* be2  = (const float*)d_in[10];
    const float* Ws   = (const float*)d_in[11];
    const float* bs   = (const float*)d_in[12];
    const float* Wa   = (const float*)d_in[13];
    const float* ba   = (const float*)d_in[14];
    float* out = (float*)d_out;

    const int SMALL_SMEM = 2 * 48 * 1024 + 1024;
    const int BIG_SMEM   = 3 * 64 * 1024 + 1024;
    cudaFuncSetAttribute(k_small_gemm<F_>, cudaFuncAttributeMaxDynamicSharedMemorySize, SMALL_SMEM);
    cudaFuncSetAttribute(k_small_gemm<HD>, cudaFuncAttributeMaxDynamicSharedMemorySize, SMALL_SMEM);
    cudaFuncSetAttribute(k_big_gemm<1>,    cudaFuncAttributeMaxDynamicSharedMemorySize, BIG_SMEM);
    cudaFuncSetAttribute(k_big_gemm<2>,    cudaFuncAttributeMaxDynamicSharedMemorySize, BIG_SMEM);

    float* WT1 = nullptr; float* WT2 = nullptr; float* H1p = nullptr;
    cudaGetSymbolAddress((void**)&WT1, g_WT1);
    cudaGetSymbolAddress((void**)&WT2, g_WT2);
    cudaGetSymbolAddress((void**)&H1p, g_H1);

    k_zero_colsum<<<B_, 256>>>();
    k_transpose<<<64, 256>>>(W1, WT1, F_);
    k_transpose<<<64, 256>>>(W2, WT2, HD);

    // Layer 1: P1^T = (X @ W1)^T ; H1 = relu(LN(A @ P1 + b1))
    k_small_gemm<F_><<<dim3(N_ / 128, B_), 128, SMALL_SMEM>>>(X, WT1);
    k_big_gemm<1><<<dim3(N_ / 256, B_), 128, BIG_SMEM>>>(A, b1, g1, be1);

    // Layer 2: P2^T = (H1 @ W2)^T ; colsum += relu(LN(A @ P2 + b2))
    k_small_gemm<HD><<<dim3(N_ / 128, B_), 128, SMALL_SMEM>>>(H1p, WT2);
    k_big_gemm<2><<<dim3(N_ / 256, B_), 128, BIG_SMEM>>>(A, b2, g2, be2);

    k_finalize<<<B_, 288>>>(gvec, Ws, bs, Wa, ba, out);
}

// round 4
// speedup vs baseline: 6.2040x; 1.2155x over previous
#include <cuda_runtime.h>
#include <cuda.h>
#include <cstdint>
#include <math.h>

#define B_   16
#define N_   2048
#define F_   64
#define HD   256
#define GD   18
#define KD   128
#define FUSE 274
#define LN_EPS 1e-5f

// tcgen05 is arch-accelerated: gate on the 'a'/family targets; plain compute_103
// passes get a SIMT fallback body (correctness insurance only).
#if defined(__CUDA_ARCH_FEAT_SM103_ALL) || defined(__CUDA_ARCH_FEAT_SM100_ALL) || \
    defined(__CUDA_ARCH_FEAT_SM101_ALL) || \
    (defined(__CUDA_ARCH_SPECIFIC__) && (__CUDA_ARCH_SPECIFIC__ >= 1000)) || \
    (defined(__CUDA_ARCH_FAMILY_SPECIFIC__) && (__CUDA_ARCH_FAMILY_SPECIFIC__ >= 1000))
#define TC_OK 1
#else
#define TC_OK 0
#endif

// ---------------------------------------------------------------------------
// Scratch (device globals; no runtime allocation allowed)
// ---------------------------------------------------------------------------
__device__ __align__(1024) float g_P[B_ * HD * N_];    // P^T  [b][c][n]
__device__ __align__(1024) float g_H1[B_ * N_ * HD];   // layer-1 out [b][n][c]
__device__ __align__(1024) float g_WT1[HD * F_];       // W1^T [c][k]
__device__ __align__(1024) float g_WT2[HD * HD];       // W2^T [c][k]
__device__ float g_colsum[B_ * HD];

// ---------------------------------------------------------------------------
// Helpers
// ---------------------------------------------------------------------------
__device__ __forceinline__ uint32_t smem_u32(const void* p) {
    uint32_t a;
    asm("{ .reg .u64 t; cvta.to.shared.u64 t, %1; cvt.u32.u64 %0, t; }" : "=r"(a) : "l"(p));
    return a;
}
#define MBAR_INIT(a, c) \
    asm volatile("mbarrier.init.shared.b64 [%0], %1;" :: "r"(a), "r"(c) : "memory")
#define MBAR_EXPECT_TX(a, n) \
    asm volatile("mbarrier.arrive.expect_tx.shared.b64 _, [%0], %1;" :: "r"(a), "r"(n) : "memory")

__device__ __forceinline__ void mbar_wait(uint32_t mbar, uint32_t parity) {
    asm volatile(
        "{\n\t.reg .pred P1;\n\t"
        "WL_%=:\n\t"
        "mbarrier.try_wait.parity.acquire.cta.shared::cta.b64 P1, [%0], %1, 0x989680;\n\t"
        "@P1 bra.uni WD_%=;\n\t"
        "bra.uni WL_%=;\n\t"
        "WD_%=:\n\t}"
        :: "r"(mbar), "r"(parity) : "memory");
}

#if TC_OK
__device__ __forceinline__ uint64_t sdesc(uint32_t addr) {
    // SW128, Blackwell version=1, SBO=64, LBO=1
    return ((2ull << 61) | (1ull << 46) | (64ull << 32) | (1ull << 16))
         | ((uint64_t)(addr >> 4) & 0x3FFF);
}
__device__ __forceinline__ void tma2d(uint32_t dst, const CUtensorMap* m, int x, int y,
                                      uint32_t mbar) {
    asm volatile(
        "cp.async.bulk.tensor.2d.shared::cta.global.tile.mbarrier::complete_tx::bytes "
        "[%0], [%1, {%2, %3}], [%4];"
        :: "r"(dst), "l"(m), "r"(x), "r"(y), "r"(mbar) : "memory");
}
#define TC_COMMIT(a) \
    asm volatile("tcgen05.commit.cta_group::1.mbarrier::arrive::one.shared::cluster.b64 [%0];" \
                 :: "r"(a) : "memory")
#define TC_ALLOC(a, n) \
    asm volatile("tcgen05.alloc.cta_group::1.sync.aligned.shared::cta.b32 [%0], %1;" \
                 :: "r"(a), "r"(n) : "memory")
#define TC_RELINQ() \
    asm volatile("tcgen05.relinquish_alloc_permit.cta_group::1.sync.aligned;")
#define TC_DEALLOC(t, n) \
    asm volatile("tcgen05.dealloc.cta_group::1.sync.aligned.b32 %0, %1;" :: "r"(t), "r"(n))
#define TC_FENCE_AFTER()  asm volatile("tcgen05.fence::after_thread_sync;" ::: "memory")
#define TC_WAIT_LD() asm volatile("tcgen05.wait::ld.sync.aligned;" ::: "memory")

// D = A @ B^T : fp32 accum, TF32 inputs (fmt=2), M=128, N=256
#define IDESC_TF32 ((1u << 4) | (2u << 7) | (2u << 10) | ((256u / 8) << 17) | ((128u / 16) << 24))

__device__ __forceinline__ void mma_tf32(uint32_t d, uint64_t ad, uint64_t bd, uint32_t acc) {
    asm volatile(
        "{\n\t.reg .pred p;\n\t"
        "setp.ne.u32 p, %4, 0;\n\t"
        "tcgen05.mma.cta_group::1.kind::tf32 [%0], %1, %2, %3, p;\n\t}"
        :: "r"(d), "l"(ad), "l"(bd), "r"(IDESC_TF32), "r"(acc) : "memory");
}

#define LDX32(r, a) \
    asm volatile( \
        "tcgen05.ld.sync.aligned.32x32b.x32.b32 " \
        "{%0, %1, %2, %3, %4, %5, %6, %7, %8, %9, %10, %11, %12, %13, %14, %15, " \
        " %16, %17, %18, %19, %20, %21, %22, %23, %24, %25, %26, %27, %28, %29, %30, %31}, [%32];" \
        : "=r"((r)[0]),  "=r"((r)[1]),  "=r"((r)[2]),  "=r"((r)[3]), \
          "=r"((r)[4]),  "=r"((r)[5]),  "=r"((r)[6]),  "=r"((r)[7]), \
          "=r"((r)[8]),  "=r"((r)[9]),  "=r"((r)[10]), "=r"((r)[11]), \
          "=r"((r)[12]), "=r"((r)[13]), "=r"((r)[14]), "=r"((r)[15]), \
          "=r"((r)[16]), "=r"((r)[17]), "=r"((r)[18]), "=r"((r)[19]), \
          "=r"((r)[20]), "=r"((r)[21]), "=r"((r)[22]), "=r"((r)[23]), \
          "=r"((r)[24]), "=r"((r)[25]), "=r"((r)[26]), "=r"((r)[27]), \
          "=r"((r)[28]), "=r"((r)[29]), "=r"((r)[30]), "=r"((r)[31]) \
        : "r"(a))
#endif // TC_OK

// ---------------------------------------------------------------------------
// misc small kernels (arch-neutral)
// ---------------------------------------------------------------------------
__global__ void k_zero_colsum() { g_colsum[blockIdx.x * 256 + threadIdx.x] = 0.f; }

__global__ void k_transpose(const float* __restrict__ W, float* __restrict__ WT, int K) {
    int c = threadIdx.x;
    for (int k = blockIdx.x; k < K; k += gridDim.x)
        WT[c * K + k] = W[k * 256 + c];
}

// ---------------------------------------------------------------------------
// Small GEMM: D[128 nodes, 256 c] = In[node, KDIM] @ WT[c, KDIM]^T ; write P^T
// Single-thread TMA + MMA mainloop.
// ---------------------------------------------------------------------------
template <int KDIM>
__global__ __launch_bounds__(128, 1)
void k_small_gemm(const __grid_constant__ CUtensorMap mapIn,
                  const __grid_constant__ CUtensorMap mapW,
                  const float* __restrict__ In, const float* __restrict__ WT) {
    const int tid = threadIdx.x;
    const int b   = blockIdx.y;
    const int m0  = blockIdx.x * 128;
    float* PTb = g_P + (size_t)b * HD * N_;

#if TC_OK
    constexpr int NK   = KDIM / 32;
    constexpr int NSTG = (NK < 3) ? NK : 3;
    constexpr int STG  = 48 * 1024;                 // A 16KB + B 32KB
    extern __shared__ char dyn[];
    const uint32_t sbase = (smem_u32(dyn) + 1023) & ~1023u;

    __shared__ __align__(8) uint64_t s_bar[7];      // full[3], empty[3], final
    __shared__ uint32_t s_tmem[1];

    const int wid  = tid >> 5;
    const int lane = tid & 31;
    const uint32_t bar0 = smem_u32(s_bar);
#define FULLB(s)  (bar0 + (s) * 8)
#define EMPTB(s)  (bar0 + 24 + (s) * 8)
#define FINALB    (bar0 + 48)

    if (tid == 0)
        for (int i = 0; i < 7; i++) MBAR_INIT(bar0 + i * 8, 1);
    if (wid == 0) { TC_ALLOC(smem_u32(s_tmem), 256); TC_RELINQ(); }
    __syncthreads();
    uint32_t tmem;
    asm volatile("ld.shared.b32 %0, [%1];" : "=r"(tmem) : "r"(smem_u32(s_tmem)));

    if (tid == 0) {
        int fp[3] = {0, 0, 0}, ep[3] = {0, 0, 0};
        const int yA = b * N_ + m0;
        auto issue = [&](int t) {
            int s = t % NSTG;
            uint32_t sa = sbase + s * STG;
            MBAR_EXPECT_TX(FULLB(s), STG);
            tma2d(sa,             &mapIn, t * 32, yA, FULLB(s));
            tma2d(sa + 16 * 1024, &mapW,  t * 32, 0,  FULLB(s));
        };
#pragma unroll
        for (int t = 0; t < NSTG; t++) issue(t);
#pragma unroll 1
        for (int t = 0; t < NK; t++) {
            int s = t % NSTG;
            mbar_wait(FULLB(s), fp[s]); fp[s] ^= 1;
            uint64_t a0 = sdesc(sbase + s * STG);
            uint64_t b0 = sdesc(sbase + s * STG + 16 * 1024);
#pragma unroll
            for (int ks = 0; ks < 4; ks++)
                mma_tf32(tmem, a0 + ks * 2, b0 + ks * 2, (t > 0 || ks > 0) ? 1u : 0u);
            TC_COMMIT(EMPTB(s));
            int tn = t + NSTG;
            if (tn < NK) { mbar_wait(EMPTB(s), ep[s]); ep[s] ^= 1; issue(tn); }
        }
        TC_COMMIT(FINALB);
    }
    mbar_wait(FINALB, 0);
    TC_FENCE_AFTER();

    // epilogue: lane = node row; reg j = channel. Per-reg stores coalesced.
    const int row = m0 + wid * 32 + lane;
#pragma unroll
    for (int c8 = 0; c8 < 8; c8++) {
        uint32_t r[32];
        LDX32(r, tmem + c8 * 32);
        TC_WAIT_LD();
#pragma unroll
        for (int j = 0; j < 32; j++)
            PTb[(size_t)(c8 * 32 + j) * N_ + row] = __uint_as_float(r[j]);
    }
    __syncthreads();
    if (wid == 0) TC_DEALLOC(tmem, 256);
#undef FULLB
#undef EMPTB
#undef FINALB
#else
    const float* Inb = In + (size_t)b * N_ * KDIM + (size_t)m0 * KDIM;
    for (int idx = tid; idx < 128 * 256; idx += 128) {
        int m = idx >> 8, c = idx & 255;
        float acc = 0.f;
        for (int k = 0; k < KDIM; k++)
            acc += Inb[(size_t)m * KDIM + k] * WT[(size_t)c * KDIM + k];
        PTb[(size_t)c * N_ + m0 + m] = acc;
    }
#endif
}

// ---------------------------------------------------------------------------
// Big GEMM + fused epilogue: D[256, 256] = A[b] @ P^T[b]^T ; y = relu(LN(D+b))
//   LAYER 1: y -> g_H1 ; LAYER 2: column-sum(y) -> g_colsum
// Single-thread TMA + MMA mainloop; 3 stages x 64KB.
// ---------------------------------------------------------------------------
template <int LAYER>
__global__ __launch_bounds__(128, 1)
void k_big_gemm(const __grid_constant__ CUtensorMap mapA,
                const __grid_constant__ CUtensorMap mapP,
                const float* __restrict__ A,
                const float* __restrict__ bias, const float* __restrict__ gamma,
                const float* __restrict__ beta) {
    extern __shared__ char dyn[];
    const int tid = threadIdx.x;
    const int b   = blockIdx.y;
    const int m0  = blockIdx.x * 256;

#if TC_OK
    constexpr int NK  = N_ / 32;            // 64
    constexpr int STG = 64 * 1024;          // A 32KB + B 32KB
    const uint32_t sbase = (smem_u32(dyn) + 1023) & ~1023u;

    __shared__ __align__(8) uint64_t s_bar[7];
    __shared__ uint32_t s_tmem[1];

    const int wid  = tid >> 5;
    const int lane = tid & 31;
    const uint32_t bar0 = smem_u32(s_bar);
#define FULLB(s)  (bar0 + (s) * 8)
#define EMPTB(s)  (bar0 + 24 + (s) * 8)
#define FINALB    (bar0 + 48)

    if (tid == 0)
        for (int i = 0; i < 7; i++) MBAR_INIT(bar0 + i * 8, 1);
    if (wid == 0) { TC_ALLOC(smem_u32(s_tmem), 512); TC_RELINQ(); }
    __syncthreads();
    uint32_t tmem;
    asm volatile("ld.shared.b32 %0, [%1];" : "=r"(tmem) : "r"(smem_u32(s_tmem)));

    if (tid == 0) {
        int fp[3] = {0, 0, 0}, ep[3] = {0, 0, 0};
        const int yA = b * N_ + m0;
        const int yB = b * HD;
        auto issue = [&](int t) {
            int s = t % 3;
            uint32_t sa = sbase + s * STG;
            MBAR_EXPECT_TX(FULLB(s), STG);
            tma2d(sa,             &mapA, t * 32, yA, FULLB(s));
            tma2d(sa + 32 * 1024, &mapP, t * 32, yB, FULLB(s));
        };
        issue(0); issue(1); issue(2);
#pragma unroll 1
        for (int t = 0; t < NK; t++) {
            int s = t % 3;
            mbar_wait(FULLB(s), fp[s]); fp[s] ^= 1;
            uint64_t a0 = sdesc(sbase + s * STG);
            uint64_t a1 = sdesc(sbase + s * STG + 16 * 1024);
            uint64_t b0 = sdesc(sbase + s * STG + 32 * 1024);
#pragma unroll
            for (int ks = 0; ks < 4; ks++) {
                uint32_t acc = (t > 0 || ks > 0) ? 1u : 0u;
                mma_tf32(tmem,       a0 + ks * 2, b0 + ks * 2, acc);
                mma_tf32(tmem + 256, a1 + ks * 2, b0 + ks * 2, acc);
            }
            TC_COMMIT(EMPTB(s));
            int tn = t + 3;
            if (tn < NK) { mbar_wait(EMPTB(s), ep[s]); ep[s] ^= 1; issue(tn); }
        }
        TC_COMMIT(FINALB);
    }
    mbar_wait(FINALB, 0);
    TC_FENCE_AFTER();

    // ---- epilogue (pipeline smem free now) ----
    float* p_bias = (float*)(dyn);
    float* p_g    = p_bias + 256;
    float* p_bt   = p_g + 256;
    float* wsc    = p_bt + 256 + (wid * 33 * 32);
    for (int i = tid; i < 256; i += 128) {
        p_bias[i] = bias[i]; p_g[i] = gamma[i]; p_bt[i] = beta[i];
    }
    __syncthreads();

#pragma unroll 1
    for (int half = 0; half < 2; half++) {
        const int row = half * 128 + wid * 32 + lane;
        const uint32_t dbase = tmem + half * 256;
        float sum = 0.f, sq = 0.f;
#pragma unroll 1
        for (int c8 = 0; c8 < 8; c8++) {
            uint32_t r[32];
            LDX32(r, dbase + c8 * 32);
            TC_WAIT_LD();
#pragma unroll
            for (int j = 0; j < 32; j++) {
                float v = __uint_as_float(r[j]) + p_bias[c8 * 32 + j];
                sum += v; sq += v * v;
            }
        }
        const float mu  = sum * (1.f / HD);
        const float var = sq * (1.f / HD) - mu * mu;
        const float rs  = rsqrtf(var + LN_EPS);

#pragma unroll 1
        for (int c8 = 0; c8 < 8; c8++) {
            uint32_t r[32];
            LDX32(r, dbase + c8 * 32);
            TC_WAIT_LD();
            float y[32];
#pragma unroll
            for (int j = 0; j < 32; j++) {
                float v = __uint_as_float(r[j]) + p_bias[c8 * 32 + j];
                y[j] = fmaxf((v - mu) * rs * p_g[c8 * 32 + j] + p_bt[c8 * 32 + j], 0.f);
            }
            if (LAYER == 1) {
                float* dst = g_H1 + ((size_t)b * N_ + m0 + row) * HD + c8 * 32;
#pragma unroll
                for (int q = 0; q < 8; q++) {
                    float4 v4 = {y[q * 4], y[q * 4 + 1], y[q * 4 + 2], y[q * 4 + 3]};
                    *(float4*)(dst + q * 4) = v4;
                }
            } else {
#pragma unroll
                for (int j = 0; j < 32; j++) wsc[lane * 33 + j] = y[j];
                __syncwarp();
                float s2 = 0.f;
#pragma unroll
                for (int r2 = 0; r2 < 32; r2++) s2 += wsc[r2 * 33 + lane];
                atomicAdd(&g_colsum[b * HD + c8 * 32 + lane], s2);
                __syncwarp();
            }
        }
    }
    __syncthreads();
    if (wid == 0) TC_DEALLOC(tmem, 512);
#undef FULLB
#undef EMPTB
#undef FINALB
#else
    // ---- SIMT fallback ----
    const float* Ab = A + (size_t)b * N_ * N_ + (size_t)m0 * N_;
    const float* Bb = g_P + (size_t)b * HD * N_;
    __shared__ float arow[N_];
    __shared__ float drow[256];
    __shared__ float red[2][4];
    const int lane = tid & 31, wid = tid >> 5;
    float csum0 = 0.f, csum1 = 0.f;

    for (int m = 0; m < 256; m++) {
        const int row = m0 + m;
        for (int i = tid; i < N_ / 4; i += 128)
            ((float4*)arow)[i] = ((const float4*)(Ab + (size_t)m * N_))[i];
        __syncthreads();
#pragma unroll
        for (int cp = 0; cp < 2; cp++) {
            int c = tid + cp * 128;
            float acc = 0.f;
            const float* Brow = Bb + (size_t)c * N_;
            for (int k = 0; k < N_; k++) acc += arow[k] * Brow[k];
            drow[c] = acc + bias[c];
        }
        __syncthreads();
        float v0 = drow[tid], v1 = drow[tid + 128];
        float s = v0 + v1, q = v0 * v0 + v1 * v1;
#pragma unroll
        for (int o = 16; o > 0; o >>= 1) {
            s += __shfl_xor_sync(0xffffffff, s, o);
            q += __shfl_xor_sync(0xffffffff, q, o);
        }
        if (lane == 0) { red[0][wid] = s; red[1][wid] = q; }
        __syncthreads();
        float ts = red[0][0] + red[0][1] + red[0][2] + red[0][3];
        float tq = red[1][0] + red[1][1] + red[1][2] + red[1][3];
        float mu = ts * (1.f / HD);
        float var = tq * (1.f / HD) - mu * mu;
        float rs = rsqrtf(var + LN_EPS);
        float y0 = fmaxf((v0 - mu) * rs * gamma[tid] + beta[tid], 0.f);
        float y1 = fmaxf((v1 - mu) * rs * gamma[tid + 128] + beta[tid + 128], 0.f);
        if (LAYER == 1) {
            g_H1[((size_t)b * N_ + row) * HD + tid]       = y0;
            g_H1[((size_t)b * N_ + row) * HD + tid + 128] = y1;
        } else {
            csum0 += y0; csum1 += y1;
        }
        __syncthreads();
    }
    if (LAYER == 2) {
        atomicAdd(&g_colsum[b * HD + tid], csum0);
        atomicAdd(&g_colsum[b * HD + tid + 128], csum1);
    }
#endif
}

// ---------------------------------------------------------------------------
// Readout + heads
// ---------------------------------------------------------------------------
__global__ __launch_bounds__(288)
void k_finalize(const float* __restrict__ gvec,
                const float* __restrict__ Ws, const float* __restrict__ bs,
                const float* __restrict__ Wa, const float* __restrict__ ba,
                float* __restrict__ out) {
    __shared__ float fused[FUSE];
    const int b = blockIdx.x;
    const int t = threadIdx.x;

    if (t < HD)        fused[t] = g_colsum[b * HD + t] * (1.f / N_);
    else if (t < FUSE) fused[t] = gvec[b * GD + (t - HD)];
    __syncthreads();

    if (t < KD) {
        float a = ba[t];
#pragma unroll 2
        for (int i = 0; i < FUSE; i++) a += fused[i] * Wa[i * KD + t];
        out[B_ + b * KD + t] = a;
    } else if (t == KD) {
        float a = bs[0];
        for (int i = 0; i < FUSE; i++) a += fused[i] * Ws[i];
        out[b] = a;
    }
}

// ---------------------------------------------------------------------------
// Host: tensor-map construction via driver entry point (no -lcuda needed)
// ---------------------------------------------------------------------------
typedef CUresult (CUDAAPI *tmap_enc_t)(
    CUtensorMap*, CUtensorMapDataType, cuuint32_t, void*,
    const cuuint64_t*, const cuuint64_t*, const cuuint32_t*, const cuuint32_t*,
    CUtensorMapInterleave, CUtensorMapSwizzle, CUtensorMapL2promotion,
    CUtensorMapFloatOOBfill);

static void make_map(tmap_enc_t enc, CUtensorMap* m, const void* ptr,
                     uint64_t d0, uint64_t d1, uint64_t stride1_bytes,
                     uint32_t box0, uint32_t box1) {
    cuuint64_t dims[2]    = {d0, d1};
    cuuint64_t strides[1] = {stride1_bytes};
    cuuint32_t box[2]     = {box0, box1};
    cuuint32_t es[2]      = {1, 1};
    enc(m, CU_TENSOR_MAP_DATA_TYPE_FLOAT32, 2, (void*)ptr, dims, strides, box, es,
        CU_TENSOR_MAP_INTERLEAVE_NONE, CU_TENSOR_MAP_SWIZZLE_128B,
        CU_TENSOR_MAP_L2_PROMOTION_L2_128B, CU_TENSOR_MAP_FLOAT_OOB_FILL_NONE);
}

extern "C" void kernel_launch(void* const* d_in, const int* in_sizes, int n_in,
                              void* d_out, int out_size) {
    const float* A    = (const float*)d_in[0];
    const float* X    = (const float*)d_in[1];
    const float* gvec = (const float*)d_in[2];
    const float* W1   = (const float*)d_in[3];
    const float* b1   = (const float*)d_in[4];
    const float* g1   = (const float*)d_in[5];
    const float* be1  = (const float*)d_in[6];
    const float* W2   = (const float*)d_in[7];
    const float* b2   = (const float*)d_in[8];
    const float* g2   = (const float*)d_in[9];
    const float* be2  = (const float*)d_in[10];
    const float* Ws   = (const float*)d_in[11];
    const float* bs   = (const float*)d_in[12];
    const float* Wa   = (const float*)d_in[13];
    const float* ba   = (const float*)d_in[14];
    float* out = (float*)d_out;

    const int SMALL_SMEM = 3 * 48 * 1024 + 1024;
    const int BIG_SMEM   = 3 * 64 * 1024 + 1024;
    cudaFuncSetAttribute(k_small_gemm<F_>, cudaFuncAttributeMaxDynamicSharedMemorySize, SMALL_SMEM);
    cudaFuncSetAttribute(k_small_gemm<HD>, cudaFuncAttributeMaxDynamicSharedMemorySize, SMALL_SMEM);
    cudaFuncSetAttribute(k_big_gemm<1>,    cudaFuncAttributeMaxDynamicSharedMemorySize, BIG_SMEM);
    cudaFuncSetAttribute(k_big_gemm<2>,    cudaFuncAttributeMaxDynamicSharedMemorySize, BIG_SMEM);

    float *WT1, *WT2, *H1p, *Pp;
    cudaGetSymbolAddress((void**)&WT1, g_WT1);
    cudaGetSymbolAddress((void**)&WT2, g_WT2);
    cudaGetSymbolAddress((void**)&H1p, g_H1);
    cudaGetSymbolAddress((void**)&Pp,  g_P);

    tmap_enc_t enc = nullptr;
#if CUDART_VERSION >= 12050
    cudaDriverEntryPointQueryResult qr;
    cudaGetDriverEntryPointByVersion("cuTensorMapEncodeTiled", (void**)&enc, 12000,
                                     cudaEnableDefault, &qr);
#else
    cudaGetDriverEntryPoint("cuTensorMapEncodeTiled", (void**)&enc, cudaEnableDefault);
#endif

    CUtensorMap mA, mP, mX, mW1, mH1, mW2;
    make_map(enc, &mA,  A,   N_, (uint64_t)N_ * B_, (uint64_t)N_ * 4, 32, 256);
    make_map(enc, &mP,  Pp,  N_, (uint64_t)HD * B_, (uint64_t)N_ * 4, 32, 256);
    make_map(enc, &mX,  X,   F_, (uint64_t)N_ * B_, (uint64_t)F_ * 4, 32, 128);
    make_map(enc, &mW1, WT1, F_, HD,                (uint64_t)F_ * 4, 32, 256);
    make_map(enc, &mH1, H1p, HD, (uint64_t)N_ * B_, (uint64_t)HD * 4, 32, 128);
    make_map(enc, &mW2, WT2, HD, HD,                (uint64_t)HD * 4, 32, 256);

    k_zero_colsum<<<B_, 256>>>();
    k_transpose<<<64, 256>>>(W1, WT1, F_);
    k_transpose<<<64, 256>>>(W2, WT2, HD);

    // Layer 1: P1^T = (X @ W1)^T ; H1 = relu(LN(A @ P1 + b1))
    k_small_gemm<F_><<<dim3(N_ / 128, B_), 128, SMALL_SMEM>>>(mX, mW1, X, WT1);
    k_big_gemm<1><<<dim3(N_ / 256, B_), 128, BIG_SMEM>>>(mA, mP, A, b1, g1, be1);

    // Layer 2: P2^T = (H1 @ W2)^T ; colsum += relu(LN(A @ P2 + b2))
    k_small_gemm<HD><<<dim3(N_ / 128, B_), 128, SMALL_SMEM>>>(mH1, mW2, H1p, WT2);
    k_big_gemm<2><<<dim3(N_ / 256, B_), 128, BIG_SMEM>>>(mA, mP, A, b2, g2, be2);

    k_finalize<<<B_, 288>>>(gvec, Ws, bs, Wa, ba, out);
}

// round 5
// speedup vs baseline: 6.3519x; 1.0238x over previous
#include <cuda_runtime.h>
#include <cuda.h>
#include <cstdint>
#include <math.h>

#define B_   16
#define N_   2048
#define F_   64
#define HD   256
#define GD   18
#define KD   128
#define FUSE 274
#define LN_EPS 1e-5f

#if defined(__CUDA_ARCH_FEAT_SM103_ALL) || defined(__CUDA_ARCH_FEAT_SM100_ALL) || \
    defined(__CUDA_ARCH_FEAT_SM101_ALL) || \
    (defined(__CUDA_ARCH_SPECIFIC__) && (__CUDA_ARCH_SPECIFIC__ >= 1000)) || \
    (defined(__CUDA_ARCH_FAMILY_SPECIFIC__) && (__CUDA_ARCH_FAMILY_SPECIFIC__ >= 1000))
#define TC_OK 1
#else
#define TC_OK 0
#endif

// ---------------------------------------------------------------------------
// Scratch (device globals; no runtime allocation allowed)
// ---------------------------------------------------------------------------
__device__ __align__(1024) float g_P[B_ * HD * N_];    // P1^T [b][c][n]
__device__ __align__(1024) float g_P2[B_ * HD * N_];   // P2^T [b][c][n]
__device__ __align__(1024) float g_WT1[HD * F_];       // W1^T [c][k]
__device__ __align__(1024) float g_WT2[HD * HD];       // W2^T [c][k]
__device__ float g_colsum[B_ * HD];

// ---------------------------------------------------------------------------
// Helpers
// ---------------------------------------------------------------------------
__device__ __forceinline__ uint32_t smem_u32(const void* p) {
    uint32_t a;
    asm("{ .reg .u64 t; cvta.to.shared.u64 t, %1; cvt.u32.u64 %0, t; }" : "=r"(a) : "l"(p));
    return a;
}
#define SWZ(x) ((x) ^ (((x) >> 3) & 0x70))
#define MBAR_INIT(a, c) \
    asm volatile("mbarrier.init.shared.b64 [%0], %1;" :: "r"(a), "r"(c) : "memory")
#define MBAR_EXPECT_TX(a, n) \
    asm volatile("mbarrier.arrive.expect_tx.shared.b64 _, [%0], %1;" :: "r"(a), "r"(n) : "memory")
#define FENCE_ASYNC() asm volatile("fence.proxy.async.shared::cta;" ::: "memory")

__device__ __forceinline__ void mbar_wait(uint32_t mbar, uint32_t parity) {
    asm volatile(
        "{\n\t.reg .pred P1;\n\t"
        "WL_%=:\n\t"
        "mbarrier.try_wait.parity.acquire.cta.shared::cta.b64 P1, [%0], %1, 0x989680;\n\t"
        "@P1 bra.uni WD_%=;\n\t"
        "bra.uni WL_%=;\n\t"
        "WD_%=:\n\t}"
        :: "r"(mbar), "r"(parity) : "memory");
}

#if TC_OK
__device__ __forceinline__ uint64_t sdesc(uint32_t addr) {
    // SW128, Blackwell version=1, SBO=64, LBO=1
    return ((2ull << 61) | (1ull << 46) | (64ull << 32) | (1ull << 16))
         | ((uint64_t)(addr >> 4) & 0x3FFF);
}
__device__ __forceinline__ void tma2d(uint32_t dst, const CUtensorMap* m, int x, int y,
                                      uint32_t mbar) {
    asm volatile(
        "cp.async.bulk.tensor.2d.shared::cta.global.tile.mbarrier::complete_tx::bytes "
        "[%0], [%1, {%2, %3}], [%4];"
        :: "r"(dst), "l"(m), "r"(x), "r"(y), "r"(mbar) : "memory");
}
#define TC_COMMIT(a) \
    asm volatile("tcgen05.commit.cta_group::1.mbarrier::arrive::one.shared::cluster.b64 [%0];" \
                 :: "r"(a) : "memory")
#define TC_ALLOC(a, n) \
    asm volatile("tcgen05.alloc.cta_group::1.sync.aligned.shared::cta.b32 [%0], %1;" \
                 :: "r"(a), "r"(n) : "memory")
#define TC_RELINQ() \
    asm volatile("tcgen05.relinquish_alloc_permit.cta_group::1.sync.aligned;")
#define TC_DEALLOC(t, n) \
    asm volatile("tcgen05.dealloc.cta_group::1.sync.aligned.b32 %0, %1;" :: "r"(t), "r"(n))
#define TC_FENCE_AFTER()  asm volatile("tcgen05.fence::after_thread_sync;" ::: "memory")
#define TC_FENCE_BEFORE() asm volatile("tcgen05.fence::before_thread_sync;" ::: "memory")
#define TC_WAIT_LD() asm volatile("tcgen05.wait::ld.sync.aligned;" ::: "memory")

// D = A @ B^T : fp32 accum, TF32 inputs (fmt=2), M=128, N=256, K=8 per MMA
#define IDESC_TF32 ((1u << 4) | (2u << 7) | (2u << 10) | ((256u / 8) << 17) | ((128u / 16) << 24))

__device__ __forceinline__ void mma_tf32(uint32_t d, uint64_t ad, uint64_t bd, uint32_t acc) {
    asm volatile(
        "{\n\t.reg .pred p;\n\t"
        "setp.ne.u32 p, %4, 0;\n\t"
        "tcgen05.mma.cta_group::1.kind::tf32 [%0], %1, %2, %3, p;\n\t}"
        :: "r"(d), "l"(ad), "l"(bd), "r"(IDESC_TF32), "r"(acc) : "memory");
}

#define LDX32(r, a) \
    asm volatile( \
        "tcgen05.ld.sync.aligned.32x32b.x32.b32 " \
        "{%0, %1, %2, %3, %4, %5, %6, %7, %8, %9, %10, %11, %12, %13, %14, %15, " \
        " %16, %17, %18, %19, %20, %21, %22, %23, %24, %25, %26, %27, %28, %29, %30, %31}, [%32];" \
        : "=r"((r)[0]),  "=r"((r)[1]),  "=r"((r)[2]),  "=r"((r)[3]), \
          "=r"((r)[4]),  "=r"((r)[5]),  "=r"((r)[6]),  "=r"((r)[7]), \
          "=r"((r)[8]),  "=r"((r)[9]),  "=r"((r)[10]), "=r"((r)[11]), \
          "=r"((r)[12]), "=r"((r)[13]), "=r"((r)[14]), "=r"((r)[15]), \
          "=r"((r)[16]), "=r"((r)[17]), "=r"((r)[18]), "=r"((r)[19]), \
          "=r"((r)[20]), "=r"((r)[21]), "=r"((r)[22]), "=r"((r)[23]), \
          "=r"((r)[24]), "=r"((r)[25]), "=r"((r)[26]), "=r"((r)[27]), \
          "=r"((r)[28]), "=r"((r)[29]), "=r"((r)[30]), "=r"((r)[31]) \
        : "r"(a))
#endif // TC_OK

// ---------------------------------------------------------------------------
__global__ void k_zero_colsum() { g_colsum[blockIdx.x * 256 + threadIdx.x] = 0.f; }

__global__ void k_transpose(const float* __restrict__ W, float* __restrict__ WT, int K) {
    int c = threadIdx.x;
    for (int k = blockIdx.x; k < K; k += gridDim.x)
        WT[c * K + k] = W[k * 256 + c];
}

// ---------------------------------------------------------------------------
// Small GEMM: P1^T[c][n] from X[n,64] @ W1T[c,64]^T. Single-thread TMA+MMA.
// ---------------------------------------------------------------------------
__global__ __launch_bounds__(128, 1)
void k_small_gemm(const __grid_constant__ CUtensorMap mapIn,
                  const __grid_constant__ CUtensorMap mapW,
                  const float* __restrict__ In, const float* __restrict__ WT) {
    const int tid = threadIdx.x;
    const int b   = blockIdx.y;
    const int m0  = blockIdx.x * 128;
    float* PTb = g_P + (size_t)b * HD * N_;

#if TC_OK
    constexpr int NK  = 2;                  // 64 / 32
    constexpr int STG = 48 * 1024;          // A 16KB + B 32KB
    extern __shared__ char dyn[];
    const uint32_t sbase = (smem_u32(dyn) + 1023) & ~1023u;

    __shared__ __align__(8) uint64_t s_bar[5];   // full[2], empty[2], final
    __shared__ uint32_t s_tmem[1];

    const int wid  = tid >> 5;
    const int lane = tid & 31;
    const uint32_t bar0 = smem_u32(s_bar);

    if (tid == 0)
        for (int i = 0; i < 5; i++) MBAR_INIT(bar0 + i * 8, 1);
    if (wid == 0) { TC_ALLOC(smem_u32(s_tmem), 256); TC_RELINQ(); }
    __syncthreads();
    uint32_t tmem;
    asm volatile("ld.shared.b32 %0, [%1];" : "=r"(tmem) : "r"(smem_u32(s_tmem)));

    if (tid == 0) {
        const int yA = b * N_ + m0;
        for (int t = 0; t < NK; t++) {
            uint32_t sa = sbase + t * STG;
            MBAR_EXPECT_TX(bar0 + t * 8, STG);
            tma2d(sa,             &mapIn, t * 32, yA, bar0 + t * 8);
            tma2d(sa + 16 * 1024, &mapW,  t * 32, 0,  bar0 + t * 8);
        }
        for (int t = 0; t < NK; t++) {
            mbar_wait(bar0 + t * 8, 0);
            uint64_t a0 = sdesc(sbase + t * STG);
            uint64_t b0 = sdesc(sbase + t * STG + 16 * 1024);
#pragma unroll
            for (int ks = 0; ks < 4; ks++)
                mma_tf32(tmem, a0 + ks * 2, b0 + ks * 2, (t > 0 || ks > 0) ? 1u : 0u);
        }
        TC_COMMIT(bar0 + 32);
    }
    mbar_wait(bar0 + 32, 0);
    TC_FENCE_AFTER();

    const int row = m0 + wid * 32 + lane;
#pragma unroll
    for (int c8 = 0; c8 < 8; c8++) {
        uint32_t r[32];
        LDX32(r, tmem + c8 * 32);
        TC_WAIT_LD();
#pragma unroll
        for (int j = 0; j < 32; j++)
            PTb[(size_t)(c8 * 32 + j) * N_ + row] = __uint_as_float(r[j]);
    }
    __syncthreads();
    if (wid == 0) TC_DEALLOC(tmem, 256);
#else
    const float* Inb = In + (size_t)b * N_ * F_ + (size_t)m0 * F_;
    for (int idx = tid; idx < 128 * 256; idx += 128) {
        int m = idx >> 8, c = idx & 255;
        float acc = 0.f;
        for (int k = 0; k < F_; k++)
            acc += Inb[(size_t)m * F_ + k] * WT[(size_t)c * F_ + k];
        PTb[(size_t)c * N_ + m0 + m] = acc;
    }
#endif
}

// ---------------------------------------------------------------------------
// Fused layer-1: D = A@P1^T^T ; y = relu(LN(D+b1)) ; P2^T = (y @ W2)^T
// Mainloop: single-thread TMA + MMA, 3 stages x 64KB.
// Epilogue: y staged in smem as A-operand; second tcgen05 GEMM vs W2T chunks.
// ---------------------------------------------------------------------------
__global__ __launch_bounds__(128, 1)
void k_fused1(const __grid_constant__ CUtensorMap mapA,
              const __grid_constant__ CUtensorMap mapP,
              const __grid_constant__ CUtensorMap mapW2,
              const float* __restrict__ A,
              const float* __restrict__ bias, const float* __restrict__ gamma,
              const float* __restrict__ beta) {
    extern __shared__ char dyn[];
    const int tid = threadIdx.x;
    const int b   = blockIdx.y;
    const int m0  = blockIdx.x * 256;

#if TC_OK
    constexpr int NK    = N_ / 32;          // 64
    constexpr int STG   = 64 * 1024;        // A 32KB + B 32KB
    constexpr int W2OFF = 128 * 1024;       // epilogue W2 stages offset
    const uint32_t sbase = (smem_u32(dyn) + 1023) & ~1023u;
    const uint32_t abase = sbase - smem_u32(dyn);    // byte offset of sbase in dyn

    __shared__ __align__(8) uint64_t s_bar[11];
    __shared__ uint32_t s_tmem[1];
    __shared__ float sb[256], sg[256], st[256];

    const int wid  = tid >> 5;
    const int lane = tid & 31;
    const uint32_t bar0 = smem_u32(s_bar);
#define FULLB(s)  (bar0 + (s) * 8)
#define EMPTB(s)  (bar0 + 24 + (s) * 8)
#define FINALB    (bar0 + 48)
#define EFB(s)    (bar0 + 56 + (s) * 8)
#define EEB       (bar0 + 72)
#define EFINB     (bar0 + 80)

    if (tid == 0)
        for (int i = 0; i < 11; i++) MBAR_INIT(bar0 + i * 8, 1);
    if (wid == 0) { TC_ALLOC(smem_u32(s_tmem), 512); TC_RELINQ(); }
    __syncthreads();
    uint32_t tmem;
    asm volatile("ld.shared.b32 %0, [%1];" : "=r"(tmem) : "r"(smem_u32(s_tmem)));

    // idle threads stage LN params during the mainloop
    if (tid != 0) {
        for (int i = tid - 1; i < 256; i += 127) {
            sb[i] = bias[i]; sg[i] = gamma[i]; st[i] = beta[i];
        }
    }

    if (tid == 0) {
        int fp[3] = {0, 0, 0}, ep[3] = {0, 0, 0};
        const int yA = b * N_ + m0;
        const int yB = b * HD;
        auto issue = [&](int t) {
            int s = t % 3;
            uint32_t sa = sbase + s * STG;
            MBAR_EXPECT_TX(FULLB(s), STG);
            tma2d(sa,             &mapA, t * 32, yA, FULLB(s));
            tma2d(sa + 32 * 1024, &mapP, t * 32, yB, FULLB(s));
        };
        issue(0); issue(1); issue(2);
#pragma unroll 1
        for (int t = 0; t < NK; t++) {
            int s = t % 3;
            mbar_wait(FULLB(s), fp[s]); fp[s] ^= 1;
            uint64_t a0 = sdesc(sbase + s * STG);
            uint64_t a1 = sdesc(sbase + s * STG + 16 * 1024);
            uint64_t b0 = sdesc(sbase + s * STG + 32 * 1024);
#pragma unroll
            for (int ks = 0; ks < 4; ks++) {
                uint32_t acc = (t > 0 || ks > 0) ? 1u : 0u;
                mma_tf32(tmem,       a0 + ks * 2, b0 + ks * 2, acc);
                mma_tf32(tmem + 256, a1 + ks * 2, b0 + ks * 2, acc);
            }
            TC_COMMIT(EMPTB(s));
            int tn = t + 3;
            if (tn < NK) { mbar_wait(EMPTB(s), ep[s]); ep[s] ^= 1; issue(tn); }
        }
        TC_COMMIT(FINALB);
    }
    mbar_wait(FINALB, 0);
    TC_FENCE_AFTER();

    // ---- fused epilogue ----
    // thread0 bookkeeping for epilogue W2 pipeline
    int efp0 = 0, efp1 = 0, eep = 0;
    auto issueW2 = [&](int chunk, int s) {
        MBAR_EXPECT_TX(EFB(s), 32768);
        tma2d(sbase + W2OFF + s * 32768, &mapW2, chunk * 32, 0, EFB(s));
    };
    if (tid == 0) { issueW2(0, 0); issueW2(1, 1); }   // mainloop stage-2 region now free

#pragma unroll 1
    for (int half = 0; half < 2; half++) {
        const int row = wid * 32 + lane;            // row within 128-half
        const uint32_t dbase = tmem + half * 256;

        // pass 1: LN statistics
        float sum = 0.f, sq = 0.f;
#pragma unroll 1
        for (int c8 = 0; c8 < 8; c8++) {
            uint32_t r[32];
            LDX32(r, dbase + c8 * 32);
            TC_WAIT_LD();
#pragma unroll
            for (int j = 0; j < 32; j++) {
                float v = __uint_as_float(r[j]) + sb[c8 * 32 + j];
                sum += v; sq += v * v;
            }
        }
        const float mu  = sum * (1.f / HD);
        const float var = sq * (1.f / HD) - mu * mu;
        const float rs  = rsqrtf(var + LN_EPS);

        // pass 2: y -> smem chunks (A-operand, SW128)
#pragma unroll 1
        for (int c8 = 0; c8 < 8; c8++) {
            uint32_t r[32];
            LDX32(r, dbase + c8 * 32);
            TC_WAIT_LD();
            float y[32];
#pragma unroll
            for (int j = 0; j < 32; j++) {
                float v = __uint_as_float(r[j]) + sb[c8 * 32 + j];
                y[j] = fmaxf((v - mu) * rs * sg[c8 * 32 + j] + st[c8 * 32 + j], 0.f);
            }
            char* ybase = dyn + abase + c8 * 16384;
#pragma unroll
            for (int q = 0; q < 8; q++) {
                float4 v4 = {y[q * 4], y[q * 4 + 1], y[q * 4 + 2], y[q * 4 + 3]};
                *(float4*)(ybase + SWZ(row * 128 + q * 16)) = v4;
            }
        }
        TC_FENCE_BEFORE();
        FENCE_ASYNC();
        __syncthreads();

        // second GEMM: D2[128, 256] = Y @ W2T^T into TMEM cols half*256
        if (tid == 0) {
#pragma unroll 1
            for (int c = 0; c < 8; c++) {
                int s = c & 1;
                if (s == 0) { mbar_wait(EFB(0), efp0 & 1); efp0++; }
                else        { mbar_wait(EFB(1), efp1 & 1); efp1++; }
                uint64_t yd = sdesc(sbase + c * 16384);
                uint64_t wd = sdesc(sbase + W2OFF + s * 32768);
#pragma unroll
                for (int ks = 0; ks < 4; ks++)
                    mma_tf32(tmem + half * 256, yd + ks * 2, wd + ks * 2,
                             (c > 0 || ks > 0) ? 1u : 0u);
                TC_COMMIT(EEB);
                mbar_wait(EEB, eep & 1); eep++;
                int next = c + 2;
                if (next < 8)            issueW2(next, s);
                else if (half == 0)      issueW2(next - 8, s);  // prefetch half1
            }
            TC_COMMIT(EFINB);
        }
        mbar_wait(EFINB, half);
        TC_FENCE_AFTER();

        // read D2, store P2^T slices
        float* PTb = g_P2 + (size_t)b * HD * N_;
        const int grow = m0 + half * 128 + row;
#pragma unroll 1
        for (int c8 = 0; c8 < 8; c8++) {
            uint32_t r[32];
            LDX32(r, dbase + c8 * 32);
            TC_WAIT_LD();
#pragma unroll
            for (int j = 0; j < 32; j++)
                PTb[(size_t)(c8 * 32 + j) * N_ + grow] = __uint_as_float(r[j]);
        }
        TC_FENCE_BEFORE();
        __syncthreads();
    }
    if (wid == 0) TC_DEALLOC(tmem, 512);
#undef FULLB
#undef EMPTB
#undef FINALB
#undef EFB
#undef EEB
#undef EFINB
#else
    // ---- SIMT fallback ----
    const float* Ab = A + (size_t)b * N_ * N_ + (size_t)m0 * N_;
    const float* Bb = g_P + (size_t)b * HD * N_;
    float* PTb = g_P2 + (size_t)b * HD * N_;
    __shared__ float arow[N_];
    __shared__ float drow[256];
    __shared__ float red[2][4];
    const int lane = tid & 31, wid = tid >> 5;

    for (int m = 0; m < 256; m++) {
        for (int i = tid; i < N_ / 4; i += 128)
            ((float4*)arow)[i] = ((const float4*)(Ab + (size_t)m * N_))[i];
        __syncthreads();
#pragma unroll
        for (int cp = 0; cp < 2; cp++) {
            int c = tid + cp * 128;
            float acc = 0.f;
            const float* Brow = Bb + (size_t)c * N_;
            for (int k = 0; k < N_; k++) acc += arow[k] * Brow[k];
            drow[c] = acc + bias[c];
        }
        __syncthreads();
        float v0 = drow[tid], v1 = drow[tid + 128];
        float s = v0 + v1, q = v0 * v0 + v1 * v1;
#pragma unroll
        for (int o = 16; o > 0; o >>= 1) {
            s += __shfl_xor_sync(0xffffffff, s, o);
            q += __shfl_xor_sync(0xffffffff, q, o);
        }
        if (lane == 0) { red[0][wid] = s; red[1][wid] = q; }
        __syncthreads();
        float ts = red[0][0] + red[0][1] + red[0][2] + red[0][3];
        float tq = red[1][0] + red[1][1] + red[1][2] + red[1][3];
        float mu = ts * (1.f / HD);
        float var = tq * (1.f / HD) - mu * mu;
        float rs = rsqrtf(var + LN_EPS);
        drow[tid]       = fmaxf((v0 - mu) * rs * gamma[tid] + beta[tid], 0.f);
        drow[tid + 128] = fmaxf((v1 - mu) * rs * gamma[tid + 128] + beta[tid + 128], 0.f);
        __syncthreads();
#pragma unroll
        for (int cp = 0; cp < 2; cp++) {
            int c = tid + cp * 128;
            float acc = 0.f;
            const float* wr = g_WT2 + (size_t)c * HD;
            for (int k = 0; k < HD; k++) acc += drow[k] * wr[k];
            PTb[(size_t)c * N_ + m0 + m] = acc;
        }
        __syncthreads();
    }
#endif
}

// ---------------------------------------------------------------------------
// Layer-2 big GEMM: D = A@P2^T^T ; colsum += relu(LN(D + b2))
// ---------------------------------------------------------------------------
__global__ __launch_bounds__(128, 1)
void k_big2(const __grid_constant__ CUtensorMap mapA,
            const __grid_constant__ CUtensorMap mapP,
            const float* __restrict__ A,
            const float* __restrict__ bias, const float* __restrict__ gamma,
            const float* __restrict__ beta) {
    extern __shared__ char dyn[];
    const int tid = threadIdx.x;
    const int b   = blockIdx.y;
    const int m0  = blockIdx.x * 256;

#if TC_OK
    constexpr int NK  = N_ / 32;
    constexpr int STG = 64 * 1024;
    const uint32_t sbase = (smem_u32(dyn) + 1023) & ~1023u;

    __shared__ __align__(8) uint64_t s_bar[7];
    __shared__ uint32_t s_tmem[1];
    __shared__ float sb[256], sg[256], st[256];

    const int wid  = tid >> 5;
    const int lane = tid & 31;
    const uint32_t bar0 = smem_u32(s_bar);
#define FULLB(s)  (bar0 + (s) * 8)
#define EMPTB(s)  (bar0 + 24 + (s) * 8)
#define FINALB    (bar0 + 48)

    if (tid == 0)
        for (int i = 0; i < 7; i++) MBAR_INIT(bar0 + i * 8, 1);
    if (wid == 0) { TC_ALLOC(smem_u32(s_tmem), 512); TC_RELINQ(); }
    __syncthreads();
    uint32_t tmem;
    asm volatile("ld.shared.b32 %0, [%1];" : "=r"(tmem) : "r"(smem_u32(s_tmem)));

    if (tid != 0) {
        for (int i = tid - 1; i < 256; i += 127) {
            sb[i] = bias[i]; sg[i] = gamma[i]; st[i] = beta[i];
        }
    }

    if (tid == 0) {
        int fp[3] = {0, 0, 0}, ep[3] = {0, 0, 0};
        const int yA = b * N_ + m0;
        const int yB = b * HD;
        auto issue = [&](int t) {
            int s = t % 3;
            uint32_t sa = sbase + s * STG;
            MBAR_EXPECT_TX(FULLB(s), STG);
            tma2d(sa,             &mapA, t * 32, yA, FULLB(s));
            tma2d(sa + 32 * 1024, &mapP, t * 32, yB, FULLB(s));
        };
        issue(0); issue(1); issue(2);
#pragma unroll 1
        for (int t = 0; t < NK; t++) {
            int s = t % 3;
            mbar_wait(FULLB(s), fp[s]); fp[s] ^= 1;
            uint64_t a0 = sdesc(sbase + s * STG);
            uint64_t a1 = sdesc(sbase + s * STG + 16 * 1024);
            uint64_t b0 = sdesc(sbase + s * STG + 32 * 1024);
#pragma unroll
            for (int ks = 0; ks < 4; ks++) {
                uint32_t acc = (t > 0 || ks > 0) ? 1u : 0u;
                mma_tf32(tmem,       a0 + ks * 2, b0 + ks * 2, acc);
                mma_tf32(tmem + 256, a1 + ks * 2, b0 + ks * 2, acc);
            }
            TC_COMMIT(EMPTB(s));
            int tn = t + 3;
            if (tn < NK) { mbar_wait(EMPTB(s), ep[s]); ep[s] ^= 1; issue(tn); }
        }
        TC_COMMIT(FINALB);
    }
    mbar_wait(FINALB, 0);
    TC_FENCE_AFTER();

    float* wsc = (float*)(dyn) + wid * 33 * 32;
#pragma unroll 1
    for (int half = 0; half < 2; half++) {
        const uint32_t dbase = tmem + half * 256;
        float sum = 0.f, sq = 0.f;
#pragma unroll 1
        for (int c8 = 0; c8 < 8; c8++) {
            uint32_t r[32];
            LDX32(r, dbase + c8 * 32);
            TC_WAIT_LD();
#pragma unroll
            for (int j = 0; j < 32; j++) {
                float v = __uint_as_float(r[j]) + sb[c8 * 32 + j];
                sum += v; sq += v * v;
            }
        }
        const float mu  = sum * (1.f / HD);
        const float var = sq * (1.f / HD) - mu * mu;
        const float rs  = rsqrtf(var + LN_EPS);

#pragma unroll 1
        for (int c8 = 0; c8 < 8; c8++) {
            uint32_t r[32];
            LDX32(r, dbase + c8 * 32);
            TC_WAIT_LD();
            float y[32];
#pragma unroll
            for (int j = 0; j < 32; j++) {
                float v = __uint_as_float(r[j]) + sb[c8 * 32 + j];
                y[j] = fmaxf((v - mu) * rs * sg[c8 * 32 + j] + st[c8 * 32 + j], 0.f);
            }
#pragma unroll
            for (int j = 0; j < 32; j++) wsc[lane * 33 + j] = y[j];
            __syncwarp();
            float s2 = 0.f;
#pragma unroll
            for (int r2 = 0; r2 < 32; r2++) s2 += wsc[r2 * 33 + lane];
            atomicAdd(&g_colsum[b * HD + c8 * 32 + lane], s2);
            __syncwarp();
        }
    }
    __syncthreads();
    if (wid == 0) TC_DEALLOC(tmem, 512);
#undef FULLB
#undef EMPTB
#undef FINALB
#else
    const float* Ab = A + (size_t)b * N_ * N_ + (size_t)m0 * N_;
    const float* Bb = g_P2 + (size_t)b * HD * N_;
    __shared__ float arow[N_];
    __shared__ float drow[256];
    __shared__ float red[2][4];
    const int lane = tid & 31, wid = tid >> 5;
    float csum0 = 0.f, csum1 = 0.f;

    for (int m = 0; m < 256; m++) {
        for (int i = tid; i < N_ / 4; i += 128)
            ((float4*)arow)[i] = ((const float4*)(Ab + (size_t)m * N_))[i];
        __syncthreads();
#pragma unroll
        for (int cp = 0; cp < 2; cp++) {
            int c = tid + cp * 128;
            float acc = 0.f;
            const float* Brow = Bb + (size_t)c * N_;
            for (int k = 0; k < N_; k++) acc += arow[k] * Brow[k];
            drow[c] = acc + bias[c];
        }
        __syncthreads();
        float v0 = drow[tid], v1 = drow[tid + 128];
        float s = v0 + v1, q = v0 * v0 + v1 * v1;
#pragma unroll
        for (int o = 16; o > 0; o >>= 1) {
            s += __shfl_xor_sync(0xffffffff, s, o);
            q += __shfl_xor_sync(0xffffffff, q, o);
        }
        if (lane == 0) { red[0][wid] = s; red[1][wid] = q; }
        __syncthreads();
        float ts = red[0][0] + red[0][1] + red[0][2] + red[0][3];
        float tq = red[1][0] + red[1][1] + red[1][2] + red[1][3];
        float mu = ts * (1.f / HD);
        float var = tq * (1.f / HD) - mu * mu;
        float rs = rsqrtf(var + LN_EPS);
        csum0 += fmaxf((v0 - mu) * rs * gamma[tid] + beta[tid], 0.f);
        csum1 += fmaxf((v1 - mu) * rs * gamma[tid + 128] + beta[tid + 128], 0.f);
        __syncthreads();
    }
    atomicAdd(&g_colsum[b * HD + tid], csum0);
    atomicAdd(&g_colsum[b * HD + tid + 128], csum1);
#endif
}

// ---------------------------------------------------------------------------
__global__ __launch_bounds__(288)
void k_finalize(const float* __restrict__ gvec,
                const float* __restrict__ Ws, const float* __restrict__ bs,
                const float* __restrict__ Wa, const float* __restrict__ ba,
                float* __restrict__ out) {
    __shared__ float fused[FUSE];
    const int b = blockIdx.x;
    const int t = threadIdx.x;

    if (t < HD)        fused[t] = g_colsum[b * HD + t] * (1.f / N_);
    else if (t < FUSE) fused[t] = gvec[b * GD + (t - HD)];
    __syncthreads();

    if (t < KD) {
        float a = ba[t];
#pragma unroll 2
        for (int i = 0; i < FUSE; i++) a += fused[i] * Wa[i * KD + t];
        out[B_ + b * KD + t] = a;
    } else if (t == KD) {
        float a = bs[0];
        for (int i = 0; i < FUSE; i++) a += fused[i] * Ws[i];
        out[b] = a;
    }
}

// ---------------------------------------------------------------------------
// Host
// ---------------------------------------------------------------------------
typedef CUresult (CUDAAPI *tmap_enc_t)(
    CUtensorMap*, CUtensorMapDataType, cuuint32_t, void*,
    const cuuint64_t*, const cuuint64_t*, const cuuint32_t*, const cuuint32_t*,
    CUtensorMapInterleave, CUtensorMapSwizzle, CUtensorMapL2promotion,
    CUtensorMapFloatOOBfill);

static void make_map(tmap_enc_t enc, CUtensorMap* m, const void* ptr,
                     uint64_t d0, uint64_t d1, uint64_t stride1_bytes,
                     uint32_t box0, uint32_t box1) {
    cuuint64_t dims[2]    = {d0, d1};
    cuuint64_t strides[1] = {stride1_bytes};
    cuuint32_t box[2]     = {box0, box1};
    cuuint32_t es[2]      = {1, 1};
    enc(m, CU_TENSOR_MAP_DATA_TYPE_FLOAT32, 2, (void*)ptr, dims, strides, box, es,
        CU_TENSOR_MAP_INTERLEAVE_NONE, CU_TENSOR_MAP_SWIZZLE_128B,
        CU_TENSOR_MAP_L2_PROMOTION_L2_128B, CU_TENSOR_MAP_FLOAT_OOB_FILL_NONE);
}

extern "C" void kernel_launch(void* const* d_in, const int* in_sizes, int n_in,
                              void* d_out, int out_size) {
    const float* A    = (const float*)d_in[0];
    const float* X    = (const float*)d_in[1];
    const float* gvec = (const float*)d_in[2];
    const float* W1   = (const float*)d_in[3];
    const float* b1   = (const float*)d_in[4];
    const float* g1   = (const float*)d_in[5];
    const float* be1  = (const float*)d_in[6];
    const float* W2   = (const float*)d_in[7];
    const float* b2   = (const float*)d_in[8];
    const float* g2   = (const float*)d_in[9];
    const float* be2  = (const float*)d_in[10];
    const float* Ws   = (const float*)d_in[11];
    const float* bs   = (const float*)d_in[12];
    const float* Wa   = (const float*)d_in[13];
    const float* ba   = (const float*)d_in[14];
    float* out = (float*)d_out;

    const int SMALL_SMEM = 2 * 48 * 1024 + 1024;
    const int BIG_SMEM   = 3 * 64 * 1024 + 1024;
    cudaFuncSetAttribute(k_small_gemm, cudaFuncAttributeMaxDynamicSharedMemorySize, SMALL_SMEM);
    cudaFuncSetAttribute(k_fused1,     cudaFuncAttributeMaxDynamicSharedMemorySize, BIG_SMEM);
    cudaFuncSetAttribute(k_big2,       cudaFuncAttributeMaxDynamicSharedMemorySize, BIG_SMEM);

    float *WT1, *WT2, *P1p, *P2p;
    cudaGetSymbolAddress((void**)&WT1, g_WT1);
    cudaGetSymbolAddress((void**)&WT2, g_WT2);
    cudaGetSymbolAddress((void**)&P1p, g_P);
    cudaGetSymbolAddress((void**)&P2p, g_P2);

    tmap_enc_t enc = nullptr;
#if CUDART_VERSION >= 12050
    cudaDriverEntryPointQueryResult qr;
    cudaGetDriverEntryPointByVersion("cuTensorMapEncodeTiled", (void**)&enc, 12000,
                                     cudaEnableDefault, &qr);
#else
    cudaGetDriverEntryPoint("cuTensorMapEncodeTiled", (void**)&enc, cudaEnableDefault);
#endif

    CUtensorMap mA, mP1, mP2, mX, mW1, mW2;
    make_map(enc, &mA,  A,   N_, (uint64_t)N_ * B_, (uint64_t)N_ * 4, 32, 256);
    make_map(enc, &mP1, P1p, N_, (uint64_t)HD * B_, (uint64_t)N_ * 4, 32, 256);
    make_map(enc, &mP2, P2p, N_, (uint64_t)HD * B_, (uint64_t)N_ * 4, 32, 256);
    make_map(enc, &mX,  X,   F_, (uint64_t)N_ * B_, (uint64_t)F_ * 4, 32, 128);
    make_map(enc, &mW1, WT1, F_, HD,                (uint64_t)F_ * 4, 32, 256);
    make_map(enc, &mW2, WT2, HD, HD,                (uint64_t)HD * 4, 32, 256);

    k_zero_colsum<<<B_, 256>>>();
    k_transpose<<<64, 256>>>(W1, WT1, F_);
    k_transpose<<<64, 256>>>(W2, WT2, HD);

    // Layer 1 (fused): P1 = (X@W1)^T ; y = relu(LN(A@P1+b1)) ; P2 = (y@W2)^T
    k_small_gemm<<<dim3(N_ / 128, B_), 128, SMALL_SMEM>>>(mX, mW1, X, WT1);
    k_fused1<<<dim3(N_ / 256, B_), 128, BIG_SMEM>>>(mA, mP1, mW2, A, b1, g1, be1);

    // Layer 2: colsum += relu(LN(A@P2 + b2))
    k_big2<<<dim3(N_ / 256, B_), 128, BIG_SMEM>>>(mA, mP2, A, b2, g2, be2);

    k_finalize<<<B_, 288>>>(gvec, Ws, bs, Wa, ba, out);
}